// round 2
// baseline (speedup 1.0000x reference)
#include <cuda_runtime.h>

// ---------------------------------------------------------------------------
// enc_mtan_classif — collapsed computation:
//   A[b,c]  = masked mean of x over t   (softmax broadcast quirk)
//   G[b,n]  = A @ Wo^T + bo
//   gi[b,j] = G @ W_ih^T + b_ih        (GRU input identical at every step)
//   GRU 128 steps, gate triples (r,z,hn of unit j) in adjacent lanes of one
//   warp -> shuffle exchange, ONE barrier per step.
//   out = MLP(hT)
// ---------------------------------------------------------------------------

#define NWARP 13
#define NTHR  416

__device__ float  g_WihT[128 * 384];        // [n][j] = W_ih[j,n]
__device__ float2 g_Wpk[NWARP * 64 * 32];   // [w][m][l] = (Whh[row,2m],Whh[row,2m+1])
__device__ float  g_W1T[128 * 300];         // [k][i] = W1[i,k]
__device__ float  g_W2T[300 * 300];         // [k][i] = W2[i,k]

__global__ void prep_kernel(const float* __restrict__ W_ih,
                            const float* __restrict__ W_hh,
                            const float* __restrict__ W1,
                            const float* __restrict__ W2) {
    int idx = blockIdx.x * blockDim.x + threadIdx.x;
    if (idx < 49152) {  // W_ih transpose
        int j = idx >> 7, k = idx & 127;
        g_WihT[k * 384 + j] = W_ih[idx];
        return;
    }
    int p = idx - 49152;
    if (p < NWARP * 64 * 32) {  // W_hh packed per (warp, m, lane)
        int w = p >> 11;        // /2048
        int rem = p & 2047;
        int m = rem >> 5, l = rem & 31;
        float2 v = make_float2(0.f, 0.f);
        if (l < 30) {
            int mt = l / 3, g = l - 3 * mt, j = w * 10 + mt;
            if (j < 128) {
                int row = g * 128 + j;
                v.x = W_hh[row * 128 + 2 * m];
                v.y = W_hh[row * 128 + 2 * m + 1];
            }
        }
        g_Wpk[p] = v;
        return;
    }
    p -= NWARP * 64 * 32;
    if (p < 38400) {  // W1 transpose
        int i = p >> 7, k = p & 127;
        g_W1T[k * 300 + i] = W1[p];
        return;
    }
    p -= 38400;
    if (p < 90000) {  // W2 transpose
        int i = p / 300, k = p - i * 300;
        g_W2T[k * 300 + i] = W2[p];
    }
}

typedef unsigned long long ull;

__device__ __forceinline__ void fma2(ull& d, ull a, ull b) {
    asm("fma.rn.f32x2 %0, %1, %2, %0;" : "+l"(d) : "l"(a), "l"(b));
}
__device__ __forceinline__ ull add2(ull a, ull b) {
    ull r;
    asm("add.rn.f32x2 %0, %1, %2;" : "=l"(r) : "l"(a), "l"(b));
    return r;
}
__device__ __forceinline__ ull pack2(float lo, float hi) {
    ull r;
    asm("mov.b64 %0, {%1, %2};" : "=l"(r) : "f"(lo), "f"(hi));
    return r;
}
__device__ __forceinline__ float2 unpack2(ull v) {
    float2 f;
    asm("mov.b64 {%0, %1}, %2;" : "=f"(f.x), "=f"(f.y) : "l"(v));
    return f;
}
__device__ __forceinline__ float rcp_fast(float x) {
    float r;
    asm("rcp.approx.f32 %0, %1;" : "=f"(r) : "f"(x));
    return r;
}
__device__ __forceinline__ float sigmoid_f(float x) {
    return rcp_fast(1.0f + __expf(-x));  // EX2 + RCP, err ~1e-7
}
__device__ __forceinline__ float tanh_f(float x) {
    // tanh(x) = 2/(1+e^{-2x}) - 1 ; saturates correctly at +/-inf exp
    float r = rcp_fast(1.0f + __expf(-2.0f * x));
    return fmaf(2.0f, r, -1.0f);
}

__global__ __launch_bounds__(NTHR, 1) void mtan_kernel(
    const float* __restrict__ x,
    const float* __restrict__ Wo, const float* __restrict__ bo,
    const float* __restrict__ b_ih, const float* __restrict__ b_hh,
    const float* __restrict__ b1, const float* __restrict__ b2,
    const float* __restrict__ W3, const float* __restrict__ b3,
    float* __restrict__ out) {
    __shared__ __align__(16) float x_s[128 * 32];
    __shared__ float red[3][NWARP][32];
    __shared__ float A_s[32];
    __shared__ __align__(16) float G_s[128];
    __shared__ __align__(16) float h_s[128];
    __shared__ float gi_s[384];
    __shared__ float y1_s[300];
    __shared__ float y2_s[300];

    const int tid = threadIdx.x;
    const int b = blockIdx.x;

    // ---- load x[b] (16KB) into smem, coalesced float4 ----
    {
        const float4* xg = reinterpret_cast<const float4*>(x + b * 4096);
        float4* xs4 = reinterpret_cast<float4*>(x_s);
        for (int i = tid; i < 1024; i += NTHR) xs4[i] = xg[i];
    }
    __syncthreads();

    // ---- masked mean A[c] over t (c>=16 -> masked mean of mask -> handled same) ----
    {
        int c = tid & 31, seg = tid >> 5;  // 13 segments
        float num = 0.f, den = 0.f, tot = 0.f;
        for (int t = seg; t < 128; t += NWARP) {
            float v = x_s[t * 32 + c];
            float m = x_s[t * 32 + 16 + (c & 15)];
            num = fmaf(m, v, num);
            den += m;
            tot += v;
        }
        red[0][seg][c] = num;
        red[1][seg][c] = den;
        red[2][seg][c] = tot;
    }
    __syncthreads();
    if (tid < 32) {
        float n = 0.f, d = 0.f, t = 0.f;
#pragma unroll
        for (int s = 0; s < NWARP; ++s) {
            n += red[0][s][tid];
            d += red[1][s][tid];
            t += red[2][s][tid];
        }
        A_s[tid] = (d > 0.5f) ? (n / d) : (t * (1.0f / 128.0f));
    }
    __syncthreads();

    // ---- G[n] = A @ Wo^T + bo ----
    if (tid < 128) {
        float acc = bo[tid];
        const float* wrow = Wo + tid * 32;
#pragma unroll
        for (int c = 0; c < 32; ++c) acc = fmaf(A_s[c], wrow[c], acc);
        G_s[tid] = acc;
    }
    __syncthreads();

    // ---- gi[row] = G @ W_ih^T + b_ih -> smem (coalesced, old mapping) ----
    if (tid < 384) {
        float a0 = b_ih[tid], a1 = 0.f, a2 = 0.f, a3 = 0.f;
#pragma unroll 4
        for (int n = 0; n < 128; n += 4) {
            a0 = fmaf(G_s[n + 0], g_WihT[(n + 0) * 384 + tid], a0);
            a1 = fmaf(G_s[n + 1], g_WihT[(n + 1) * 384 + tid], a1);
            a2 = fmaf(G_s[n + 2], g_WihT[(n + 2) * 384 + tid], a2);
            a3 = fmaf(G_s[n + 3], g_WihT[(n + 3) * 384 + tid], a3);
        }
        gi_s[tid] = ((a0 + a1) + (a2 + a3));
    }
    __syncthreads();

    // ---- GRU thread mapping: warp w, lanes 0..29 = 10 (r,z,hn) triples ----
    const int w = tid >> 5, l = tid & 31;
    const int mt = l / 3;
    const int g = l - 3 * mt;
    const int j = w * 10 + mt;
    const bool valid = (l < 30) && (j < 128);
    const int row = valid ? (g * 128 + j) : 0;
    const bool isH = valid && (g == 2);
    const int base = l - g;  // lane of the r gate in this triple

    float e, gin = 0.f;
    if (g == 2) {
        gin = gi_s[row];   // inn + b_in (constant per step)
        e = b_hh[row];     // hn-dot bias
    } else {
        e = gi_s[row] + b_hh[row];  // r,z: fold everything
    }

    // ---- W_hh row -> registers (coalesced via packed layout), f32x2 ----
    ull wr[64];
    {
        const float2* wp = g_Wpk + (w << 11) + l;
#pragma unroll
        for (int m = 0; m < 64; ++m) {
            float2 t = wp[m << 5];
            wr[m] = pack2(t.x, t.y);
        }
    }

    if (tid < 128) h_s[tid] = 0.f;
    float hj = 0.f;
    __syncthreads();

    const ulonglong2* hs2 = reinterpret_cast<const ulonglong2*>(h_s);

    // ---- 128 GRU steps, ONE barrier per step ----
#pragma unroll 1
    for (int step = 0; step < 128; ++step) {
        ull a0 = 0ULL, a1 = 0ULL, a2 = 0ULL, a3 = 0ULL;
#pragma unroll
        for (int i = 0; i < 32; i += 2) {
            ulonglong2 h0 = hs2[i];
            ulonglong2 h1 = hs2[i + 1];
            fma2(a0, wr[2 * i + 0], h0.x);
            fma2(a1, wr[2 * i + 1], h0.y);
            fma2(a2, wr[2 * i + 2], h1.x);
            fma2(a3, wr[2 * i + 3], h1.y);
        }
        ull s = add2(add2(a0, a1), add2(a2, a3));
        float2 f = unpack2(s);
        float dot = (f.x + f.y) + e;
        float v = (g == 2) ? dot : sigmoid_f(dot);
        // intra-warp gate exchange (converged: full mask)
        float rv = __shfl_sync(0xffffffffu, v, base);
        float zv = __shfl_sync(0xffffffffu, v, base + 1);
        if (isH) {
            float n = tanh_f(fmaf(rv, dot, gin));
            hj = n + zv * (hj - n);
            h_s[j] = hj;
        }
        __syncthreads();
    }

    // ---- MLP head: 128 -> 300 -> 300 -> 2 ----
    if (tid < 300) {
        float a0 = b1[tid], a1 = 0.f, a2 = 0.f, a3 = 0.f;
#pragma unroll 4
        for (int k = 0; k < 128; k += 4) {
            a0 = fmaf(h_s[k + 0], g_W1T[(k + 0) * 300 + tid], a0);
            a1 = fmaf(h_s[k + 1], g_W1T[(k + 1) * 300 + tid], a1);
            a2 = fmaf(h_s[k + 2], g_W1T[(k + 2) * 300 + tid], a2);
            a3 = fmaf(h_s[k + 3], g_W1T[(k + 3) * 300 + tid], a3);
        }
        y1_s[tid] = fmaxf((a0 + a1) + (a2 + a3), 0.f);
    }
    __syncthreads();
    if (tid < 300) {
        float a0 = b2[tid], a1 = 0.f, a2 = 0.f, a3 = 0.f;
#pragma unroll 4
        for (int k = 0; k < 300; k += 4) {
            a0 = fmaf(y1_s[k + 0], g_W2T[(k + 0) * 300 + tid], a0);
            a1 = fmaf(y1_s[k + 1], g_W2T[(k + 1) * 300 + tid], a1);
            a2 = fmaf(y1_s[k + 2], g_W2T[(k + 2) * 300 + tid], a2);
            a3 = fmaf(y1_s[k + 3], g_W2T[(k + 3) * 300 + tid], a3);
        }
        y2_s[tid] = fmaxf((a0 + a1) + (a2 + a3), 0.f);
    }
    __syncthreads();
    {
        int wo = tid >> 5, lo = tid & 31;
        if (wo < 2) {
            float a = 0.f;
            for (int k = lo; k < 300; k += 32)
                a = fmaf(y2_s[k], W3[wo * 300 + k], a);
#pragma unroll
            for (int off = 16; off; off >>= 1)
                a += __shfl_down_sync(0xffffffffu, a, off);
            if (lo == 0) out[b * 2 + wo] = a + b3[wo];
        }
    }
}

extern "C" void kernel_launch(void* const* d_in, const int* in_sizes, int n_in,
                              void* d_out, int out_size) {
    (void)in_sizes;
    (void)n_in;
    (void)out_size;
    const float* x = (const float*)d_in[0];
    // d_in[1..9] (query_p, time-embedding + Q/K proj weights) are provably
    // dead: the broadcast quirk makes softmax uniform over valid mask slots.
    const float* Wo = (const float*)d_in[10];
    const float* bo = (const float*)d_in[11];
    const float* W_ih = (const float*)d_in[12];
    const float* W_hh = (const float*)d_in[13];
    const float* b_ih = (const float*)d_in[14];
    const float* b_hh = (const float*)d_in[15];
    const float* W1 = (const float*)d_in[16];
    const float* b1 = (const float*)d_in[17];
    const float* W2 = (const float*)d_in[18];
    const float* b2 = (const float*)d_in[19];
    const float* W3 = (const float*)d_in[20];
    const float* b3 = (const float*)d_in[21];
    float* out = (float*)d_out;

    const int total = 49152 + NWARP * 64 * 32 + 38400 + 90000;
    prep_kernel<<<(total + 255) / 256, 256>>>(W_ih, W_hh, W1, W2);
    mtan_kernel<<<128, NTHR>>>(x, Wo, bo, b_ih, b_hh, b1, b2, W3, b3, out);
}

// round 3
// speedup vs baseline: 2.6444x; 2.6444x over previous
#include <cuda_runtime.h>

// ---------------------------------------------------------------------------
// enc_mtan_classif — collapsed computation:
//   A[b,c]  = masked mean of x over t (softmax broadcast quirk kills Q/K path)
//   G[b,n]  = A @ Wo^T + bo
//   gi[b,j] = G @ W_ih^T + b_ih       (GRU input identical at every step)
//   GRU 128 steps: quad-of-lanes per hidden unit:
//     lane q of quad computes k-quarter q (32 dims) of rows {r,z,hn} of unit j
//     -> 8 LDS.128 + 48 fma2 per thread per step, 2 shfl_xor quad reduce,
//        gates combined in-lane, ONE barrier per step.
//   out = MLP(hT)
// ---------------------------------------------------------------------------

#define NTHR 512  // 16 warps x 8 units = 128 units

__device__ float  g_WihT[128 * 384];      // [n][j] = W_ih[j,n]
__device__ float2 g_Wq[16 * 3 * 16 * 32]; // [w][g][m][l] packed W_hh pairs
__device__ float  g_W1T[128 * 300];       // [k][i] = W1[i,k]
__device__ float  g_W2T[300 * 300];       // [k][i] = W2[i,k]

__global__ void prep_kernel(const float* __restrict__ W_ih,
                            const float* __restrict__ W_hh,
                            const float* __restrict__ W1,
                            const float* __restrict__ W2) {
    int idx = blockIdx.x * blockDim.x + threadIdx.x;
    if (idx < 49152) {  // W_ih transpose
        int j = idx >> 7, k = idx & 127;
        g_WihT[k * 384 + j] = W_ih[idx];
        return;
    }
    int p = idx - 49152;
    if (p < 24576) {  // W_hh quad-packed
        int w = p / 1536;
        int r1 = p - w * 1536;
        int g = r1 >> 9;          // /512
        int r2 = r1 & 511;
        int m = r2 >> 5, l = r2 & 31;
        int j = w * 8 + (l >> 2);
        int q = l & 3;
        int row = g * 128 + j;
        int col = q * 32 + 2 * m;
        g_Wq[p] = make_float2(W_hh[row * 128 + col], W_hh[row * 128 + col + 1]);
        return;
    }
    p -= 24576;
    if (p < 38400) {  // W1 transpose
        int i = p >> 7, k = p & 127;
        g_W1T[k * 300 + i] = W1[p];
        return;
    }
    p -= 38400;
    if (p < 90000) {  // W2 transpose
        int i = p / 300, k = p - i * 300;
        g_W2T[k * 300 + i] = W2[p];
    }
}

typedef unsigned long long ull;

__device__ __forceinline__ void fma2(ull& d, ull a, ull b) {
    asm("fma.rn.f32x2 %0, %1, %2, %0;" : "+l"(d) : "l"(a), "l"(b));
}
__device__ __forceinline__ ull pack2(float lo, float hi) {
    ull r;
    asm("mov.b64 %0, {%1, %2};" : "=l"(r) : "f"(lo), "f"(hi));
    return r;
}
__device__ __forceinline__ float2 unpack2(ull v) {
    float2 f;
    asm("mov.b64 {%0, %1}, %2;" : "=f"(f.x), "=f"(f.y) : "l"(v));
    return f;
}
__device__ __forceinline__ float rcp_fast(float x) {
    float r;
    asm("rcp.approx.f32 %0, %1;" : "=f"(r) : "f"(x));
    return r;
}
__device__ __forceinline__ float sigmoid_f(float x) {
    return rcp_fast(1.0f + __expf(-x));
}
__device__ __forceinline__ float tanh_f(float x) {
    float r = rcp_fast(1.0f + __expf(-2.0f * x));
    return fmaf(2.0f, r, -1.0f);
}

__global__ __launch_bounds__(NTHR, 1) void mtan_kernel(
    const float* __restrict__ x,
    const float* __restrict__ Wo, const float* __restrict__ bo,
    const float* __restrict__ b_ih, const float* __restrict__ b_hh,
    const float* __restrict__ b1, const float* __restrict__ b2,
    const float* __restrict__ W3, const float* __restrict__ b3,
    float* __restrict__ out) {
    __shared__ __align__(16) float x_s[128 * 32];
    __shared__ float red[3][16][32];
    __shared__ float A_s[32];
    __shared__ __align__(16) float G_s[128];
    __shared__ __align__(16) float h_s[4 * 36];  // quarter-padded (36 floats/q)
    __shared__ float gi_s[384];
    __shared__ float y1_s[300];
    __shared__ float y2_s[300];

    const int tid = threadIdx.x;
    const int b = blockIdx.x;

    // ---- load x[b] (16KB) into smem, coalesced float4 ----
    {
        const float4* xg = reinterpret_cast<const float4*>(x + b * 4096);
        float4* xs4 = reinterpret_cast<float4*>(x_s);
        for (int i = tid; i < 1024; i += NTHR) xs4[i] = xg[i];
    }
    __syncthreads();

    // ---- masked mean A[c] over t ----
    {
        int c = tid & 31, seg = tid >> 5;  // 16 segments x 8 t's
        float num = 0.f, den = 0.f, tot = 0.f;
        for (int t = seg; t < 128; t += 16) {
            float v = x_s[t * 32 + c];
            float m = x_s[t * 32 + 16 + (c & 15)];
            num = fmaf(m, v, num);
            den += m;
            tot += v;
        }
        red[0][seg][c] = num;
        red[1][seg][c] = den;
        red[2][seg][c] = tot;
    }
    __syncthreads();
    if (tid < 32) {
        float n = 0.f, d = 0.f, t = 0.f;
#pragma unroll
        for (int s = 0; s < 16; ++s) {
            n += red[0][s][tid];
            d += red[1][s][tid];
            t += red[2][s][tid];
        }
        A_s[tid] = (d > 0.5f) ? (n / d) : (t * (1.0f / 128.0f));
    }
    __syncthreads();

    // ---- G[n] = A @ Wo^T + bo ----
    if (tid < 128) {
        float acc = bo[tid];
        const float* wrow = Wo + tid * 32;
#pragma unroll
        for (int c = 0; c < 32; ++c) acc = fmaf(A_s[c], wrow[c], acc);
        G_s[tid] = acc;
    }
    __syncthreads();

    // ---- gi[row] = G @ W_ih^T + b_ih -> smem (coalesced) ----
    if (tid < 384) {
        float a0 = b_ih[tid], a1 = 0.f, a2 = 0.f, a3 = 0.f;
#pragma unroll 4
        for (int n = 0; n < 128; n += 4) {
            a0 = fmaf(G_s[n + 0], g_WihT[(n + 0) * 384 + tid], a0);
            a1 = fmaf(G_s[n + 1], g_WihT[(n + 1) * 384 + tid], a1);
            a2 = fmaf(G_s[n + 2], g_WihT[(n + 2) * 384 + tid], a2);
            a3 = fmaf(G_s[n + 3], g_WihT[(n + 3) * 384 + tid], a3);
        }
        gi_s[tid] = ((a0 + a1) + (a2 + a3));
    }
    // zero-init padded h while we're here
    if (tid < 144) h_s[tid] = 0.f;
    __syncthreads();

    // ---- GRU mapping: warp w, quad (l>>2) -> unit j; lane q = l&3 -> quarter
    const int w = tid >> 5, l = tid & 31;
    const int j = w * 8 + (l >> 2);
    const int q = l & 3;
    const int qbase = q * 36;                       // float offset of my quarter
    const int hoff = (j >> 5) * 36 + (j & 31);      // where unit j's h lives
    const bool leader = (q == 0);

    const float e0 = gi_s[j] + b_hh[j];             // r
    const float e1 = gi_s[128 + j] + b_hh[128 + j]; // z
    const float e2 = b_hh[256 + j];                 // hn dot bias
    const float gin = gi_s[256 + j];                // inn + b_in

    // ---- W_hh -> 48 packed regs (coalesced one-time load) ----
    ull wr[48];
    {
        const float2* wp = g_Wq + (w * 3) * 512 + l;
#pragma unroll
        for (int g = 0; g < 3; ++g)
#pragma unroll
            for (int m = 0; m < 16; ++m) {
                float2 t = wp[g * 512 + m * 32];
                wr[g * 16 + m] = pack2(t.x, t.y);
            }
    }

    float hj = 0.f;
    __syncthreads();

    // ---- 128 GRU steps, one barrier per step ----
#pragma unroll 1
    for (int step = 0; step < 128; ++step) {
        ull a0 = 0ULL, a1 = 0ULL, a2 = 0ULL;
#pragma unroll
        for (int c = 0; c < 8; ++c) {
            float4 hv = *reinterpret_cast<const float4*>(h_s + qbase + 4 * c);
            ull hlo = pack2(hv.x, hv.y);
            ull hhi = pack2(hv.z, hv.w);
            fma2(a0, wr[2 * c], hlo);
            fma2(a1, wr[16 + 2 * c], hlo);
            fma2(a2, wr[32 + 2 * c], hlo);
            fma2(a0, wr[2 * c + 1], hhi);
            fma2(a1, wr[16 + 2 * c + 1], hhi);
            fma2(a2, wr[32 + 2 * c + 1], hhi);
        }
        float2 f0 = unpack2(a0), f1 = unpack2(a1), f2 = unpack2(a2);
        float d0 = f0.x + f0.y, d1 = f1.x + f1.y, d2 = f2.x + f2.y;
        // quad reduction (partials of the 4 k-quarters)
        d0 += __shfl_xor_sync(0xffffffffu, d0, 1);
        d1 += __shfl_xor_sync(0xffffffffu, d1, 1);
        d2 += __shfl_xor_sync(0xffffffffu, d2, 1);
        d0 += __shfl_xor_sync(0xffffffffu, d0, 2);
        d1 += __shfl_xor_sync(0xffffffffu, d1, 2);
        d2 += __shfl_xor_sync(0xffffffffu, d2, 2);
        float r = sigmoid_f(d0 + e0);
        float z = sigmoid_f(d1 + e1);
        float n = tanh_f(fmaf(r, d2 + e2, gin));
        hj = n + z * (hj - n);
        if (leader) h_s[hoff] = hj;
        __syncthreads();
    }

    // gather final h into contiguous y-space via gi_s scratch (unpadded view)
    if (leader) gi_s[j] = hj;
    __syncthreads();
    const float* hfin = gi_s;

    // ---- MLP head: 128 -> 300 -> 300 -> 2 ----
    if (tid < 300) {
        float a0 = b1[tid], a1 = 0.f, a2 = 0.f, a3 = 0.f;
#pragma unroll 4
        for (int k = 0; k < 128; k += 4) {
            a0 = fmaf(hfin[k + 0], g_W1T[(k + 0) * 300 + tid], a0);
            a1 = fmaf(hfin[k + 1], g_W1T[(k + 1) * 300 + tid], a1);
            a2 = fmaf(hfin[k + 2], g_W1T[(k + 2) * 300 + tid], a2);
            a3 = fmaf(hfin[k + 3], g_W1T[(k + 3) * 300 + tid], a3);
        }
        y1_s[tid] = fmaxf((a0 + a1) + (a2 + a3), 0.f);
    }
    __syncthreads();
    if (tid < 300) {
        float a0 = b2[tid], a1 = 0.f, a2 = 0.f, a3 = 0.f;
#pragma unroll 4
        for (int k = 0; k < 300; k += 4) {
            a0 = fmaf(y1_s[k + 0], g_W2T[(k + 0) * 300 + tid], a0);
            a1 = fmaf(y1_s[k + 1], g_W2T[(k + 1) * 300 + tid], a1);
            a2 = fmaf(y1_s[k + 2], g_W2T[(k + 2) * 300 + tid], a2);
            a3 = fmaf(y1_s[k + 3], g_W2T[(k + 3) * 300 + tid], a3);
        }
        y2_s[tid] = fmaxf((a0 + a1) + (a2 + a3), 0.f);
    }
    __syncthreads();
    {
        int wo = tid >> 5, lo = tid & 31;
        if (wo < 2) {
            float a = 0.f;
            for (int k = lo; k < 300; k += 32)
                a = fmaf(y2_s[k], W3[wo * 300 + k], a);
#pragma unroll
            for (int off = 16; off; off >>= 1)
                a += __shfl_down_sync(0xffffffffu, a, off);
            if (lo == 0) out[b * 2 + wo] = a + b3[wo];
        }
    }
}

extern "C" void kernel_launch(void* const* d_in, const int* in_sizes, int n_in,
                              void* d_out, int out_size) {
    (void)in_sizes;
    (void)n_in;
    (void)out_size;
    const float* x = (const float*)d_in[0];
    // d_in[1..9] (query_p, time-embedding + Q/K proj weights) are provably
    // dead: the broadcast quirk makes softmax uniform over valid mask slots.
    const float* Wo = (const float*)d_in[10];
    const float* bo = (const float*)d_in[11];
    const float* W_ih = (const float*)d_in[12];
    const float* W_hh = (const float*)d_in[13];
    const float* b_ih = (const float*)d_in[14];
    const float* b_hh = (const float*)d_in[15];
    const float* W1 = (const float*)d_in[16];
    const float* b1 = (const float*)d_in[17];
    const float* W2 = (const float*)d_in[18];
    const float* b2 = (const float*)d_in[19];
    const float* W3 = (const float*)d_in[20];
    const float* b3 = (const float*)d_in[21];
    float* out = (float*)d_out;

    const int total = 49152 + 24576 + 38400 + 90000;
    prep_kernel<<<(total + 255) / 256, 256>>>(W_ih, W_hh, W1, W2);
    mtan_kernel<<<128, NTHR>>>(x, Wo, bo, b_ih, b_hh, b1, b2, W3, b3, out);
}